// round 4
// baseline (speedup 1.0000x reference)
#include <cuda_runtime.h>

// Problem constants (fixed by the reference)
#define Nn   100000
#define Ee   200000
#define Gg   2000
#define Dd   300
#define D2   600
#define LL   5
#define FT   512
#define FT2  256
#define EPSC 1e-5f

// ---------------- scratch (static device globals; no allocation) ----------------
__device__ float g_h[Nn * Dd];      // node features
__device__ float g_agg[Nn * Dd];    // aggregated messages / fused attention
__device__ float g_mid[Nn * D2];    // MLP hidden
__device__ float g_hin[Nn * Dd];    // gaussian basis segment sum
__device__ int   g_cnt[Nn];         // in-degree counts
__device__ float g_stats[2 * Dd];   // BN sum / sumsq
__device__ float g_gsum[Gg * Dd];   // pooled sums
__device__ float g_gcnt[Gg];        // pooled counts
__device__ float g_hg[Gg * Dd];     // pooled means
__device__ float g_t1[Gg * FT];     // output-MLP hidden

// ---------------- small utility kernels ----------------
__global__ void k_zero_f(float* __restrict__ p, int n) {
    int i = blockIdx.x * blockDim.x + threadIdx.x;
    if (i < n) p[i] = 0.f;
}
__global__ void k_zero_i(int* __restrict__ p, int n) {
    int i = blockIdx.x * blockDim.x + threadIdx.x;
    if (i < n) p[i] = 0;
}

// degree counts
__global__ void k_count(const int* __restrict__ dst) {
    int e = blockIdx.x * blockDim.x + threadIdx.x;
    if (e < Ee) atomicAdd(&g_cnt[dst[e]], 1);
}

// gaussian basis + scatter to h_in
__global__ void k_gauss(const float* __restrict__ dist, const int* __restrict__ dst,
                        const float* __restrict__ means, const float* __restrict__ stds) {
    int idx = blockIdx.x * blockDim.x + threadIdx.x;
    if (idx >= Ee * Dd) return;
    int e = idx / Dd;
    int d = idx - e * Dd;
    float sd = fabsf(stds[d]) + 0.01f;
    float z  = (dist[e] - means[d]) / sd;
    float g  = __expf(-0.5f * z * z) / (2.5066268f * sd);
    atomicAdd(&g_hin[dst[e] * Dd + d], g);
}

// h_in *= exp(scale_param)[degree]
__global__ void k_scale(const float* __restrict__ scale_param) {
    int idx = blockIdx.x * blockDim.x + threadIdx.x;
    if (idx >= Nn * Dd) return;
    int n = idx / Dd;
    int d = idx - n * Dd;
    int c = g_cnt[n] - 1;
    c = c < 0 ? 0 : (c > 3 ? 3 : c);
    g_hin[idx] *= __expf(scale_param[c * Dd + d]);
}

// atom-embedding attention -> fused (writes g_agg). One warp per node.
__global__ void k_attn(const int* __restrict__ x, const float* __restrict__ atom_emb,
                       const float* __restrict__ att_vec) {
    int warp = (blockIdx.x * blockDim.x + threadIdx.x) >> 5;
    int lane = threadIdx.x & 31;
    if (warp >= Nn) return;
    const int n = warp;
    int xi[9];
#pragma unroll
    for (int f = 0; f < 9; f++) xi[f] = x[n * 9 + f];
    float s[9];
#pragma unroll
    for (int f = 0; f < 9; f++) {
        const float* emb = atom_emb + (f * 119 + xi[f]) * Dd;
        float p = 0.f;
        for (int d = lane; d < Dd; d += 32) p += emb[d] * att_vec[d];
#pragma unroll
        for (int o = 16; o > 0; o >>= 1) p += __shfl_xor_sync(0xffffffffu, p, o);
        s[f] = p;
    }
    float m = s[0];
#pragma unroll
    for (int f = 1; f < 9; f++) m = fmaxf(m, s[f]);
    float w[9], tot = 0.f;
#pragma unroll
    for (int f = 0; f < 9; f++) { w[f] = __expf(s[f] - m); tot += w[f]; }
    float inv = 1.f / tot;
#pragma unroll
    for (int f = 0; f < 9; f++) w[f] *= inv;
    for (int d = lane; d < Dd; d += 32) {
        float v = 0.f;
#pragma unroll
        for (int f = 0; f < 9; f++) v += w[f] * atom_emb[(f * 119 + xi[f]) * Dd + d];
        g_agg[n * Dd + d] = v;
    }
}

// agg = h + e_loop (self-loop message), ee = edge_emb for layer l: [3][5][Dd]
__global__ void k_agginit(const float* __restrict__ ee) {
    int idx = blockIdx.x * blockDim.x + threadIdx.x;
    if (idx >= Nn * Dd) return;
    int d = idx % Dd;
    float el = ee[4 * Dd + d] + ee[5 * Dd + d] + ee[10 * Dd + d];
    g_agg[idx] = g_h[idx] + el;
}

// scatter real-edge messages: agg[dst] += h[src] + e(attr)
__global__ void k_scatter(const int* __restrict__ src, const int* __restrict__ dst,
                          const int* __restrict__ attr, const float* __restrict__ ee) {
    int idx = blockIdx.x * blockDim.x + threadIdx.x;
    if (idx >= Ee * Dd) return;
    int e = idx / Dd;
    int d = idx - e * Dd;
    int a0 = attr[e * 3 + 0];
    int a1 = attr[e * 3 + 1];
    int a2 = attr[e * 3 + 2];
    float ev = ee[a0 * Dd + d] + ee[(5 + a1) * Dd + d] + ee[(10 + a2) * Dd + d];
    atomicAdd(&g_agg[dst[e] * Dd + d], g_h[src[e] * Dd + d] + ev);
}

// BN stats: per-channel sum + sumsq via smem bins
__global__ void k_bnstats() {
    __shared__ float ssum[Dd];
    __shared__ float ssq[Dd];
    for (int i = threadIdx.x; i < Dd; i += blockDim.x) { ssum[i] = 0.f; ssq[i] = 0.f; }
    __syncthreads();
    int total = Nn * Dd;
    int stride = gridDim.x * blockDim.x;
    for (int idx = blockIdx.x * blockDim.x + threadIdx.x; idx < total; idx += stride) {
        float v = g_h[idx];
        int d = idx % Dd;
        atomicAdd(&ssum[d], v);
        atomicAdd(&ssq[d], v * v);
    }
    __syncthreads();
    for (int i = threadIdx.x; i < Dd; i += blockDim.x) {
        atomicAdd(&g_stats[i], ssum[i]);
        atomicAdd(&g_stats[Dd + i], ssq[i]);
    }
}

__global__ void k_bnapply(const float* __restrict__ gamma, const float* __restrict__ beta,
                          int do_relu) {
    int idx = blockIdx.x * blockDim.x + threadIdx.x;
    if (idx >= Nn * Dd) return;
    int d = idx % Dd;
    float mu  = g_stats[d] * (1.0f / Nn);
    float var = g_stats[Dd + d] * (1.0f / Nn) - mu * mu;
    float rs  = rsqrtf(var + EPSC);
    float v = gamma[d] * (g_h[idx] - mu) * rs + beta[d];
    if (do_relu) v = fmaxf(v, 0.f);
    g_h[idx] = v;
}

// graph pooling
__global__ void k_pool(const int* __restrict__ batch) {
    int idx = blockIdx.x * blockDim.x + threadIdx.x;
    if (idx >= Nn * Dd) return;
    int n = idx / Dd;
    int d = idx - n * Dd;
    atomicAdd(&g_gsum[batch[n] * Dd + d], g_h[idx]);
}
__global__ void k_poolcnt(const int* __restrict__ batch) {
    int n = blockIdx.x * blockDim.x + threadIdx.x;
    if (n < Nn) atomicAdd(&g_gcnt[batch[n]], 1.f);
}
__global__ void k_pooldiv() {
    int idx = blockIdx.x * blockDim.x + threadIdx.x;
    if (idx >= Gg * Dd) return;
    int g = idx / Dd;
    g_hg[idx] = g_gsum[idx] / fmaxf(g_gcnt[g], 1.f);
}

// ---------------- fp32 SGEMM: C = A(MxK) @ B(KxN) + bias [+ extra] [relu] ----------------
template <bool RELU, bool EXTRA>
__global__ __launch_bounds__(256, 2) void sgemm(const float* __restrict__ A,
                                                const float* __restrict__ B,
                                                const float* __restrict__ bias,
                                                const float* __restrict__ extra,
                                                float* __restrict__ C,
                                                int M, int K, int Nc) {
    const int BM = 128, BN = 128, BK = 8;
    __shared__ float As[BK][BM];
    __shared__ float Bs[BK][BN];
    int bm = blockIdx.y * BM;
    int bn = blockIdx.x * BN;
    int tid = threadIdx.x;
    int tx = tid & 15;
    int ty = tid >> 4;
    float acc[8][8];
#pragma unroll
    for (int i = 0; i < 8; i++)
#pragma unroll
        for (int j = 0; j < 8; j++) acc[i][j] = 0.f;

    for (int k0 = 0; k0 < K; k0 += BK) {
        {
            int r  = tid >> 1;
            int kk = (tid & 1) * 4;
            int grow = bm + r;
#pragma unroll
            for (int i = 0; i < 4; i++) {
                int gk = k0 + kk + i;
                float v = 0.f;
                if (grow < M && gk < K) v = A[grow * K + gk];
                As[kk + i][r] = v;
            }
        }
        {
            int kk = tid >> 5;
            int c  = (tid & 31) * 4;
            int gk = k0 + kk;
#pragma unroll
            for (int i = 0; i < 4; i++) {
                int gcol = bn + c + i;
                float v = 0.f;
                if (gk < K && gcol < Nc) v = B[gk * Nc + gcol];
                Bs[kk][c + i] = v;
            }
        }
        __syncthreads();
#pragma unroll
        for (int k = 0; k < BK; k++) {
            float a[8], b[8];
            *(float4*)&a[0] = *(const float4*)&As[k][ty * 8];
            *(float4*)&a[4] = *(const float4*)&As[k][ty * 8 + 4];
            *(float4*)&b[0] = *(const float4*)&Bs[k][tx * 8];
            *(float4*)&b[4] = *(const float4*)&Bs[k][tx * 8 + 4];
#pragma unroll
            for (int i = 0; i < 8; i++)
#pragma unroll
                for (int j = 0; j < 8; j++) acc[i][j] = fmaf(a[i], b[j], acc[i][j]);
        }
        __syncthreads();
    }
#pragma unroll
    for (int i = 0; i < 8; i++) {
        int row = bm + ty * 8 + i;
        if (row >= M) continue;
#pragma unroll
        for (int j = 0; j < 8; j++) {
            int col = bn + tx * 8 + j;
            if (col >= Nc) continue;
            float v = acc[i][j] + bias[col];
            if (EXTRA) v += extra[row * Nc + col];
            if (RELU) v = fmaxf(v, 0.f);
            C[row * Nc + col] = v;
        }
    }
}

static inline dim3 gemm_grid(int M, int Nc) {
    return dim3((Nc + 127) / 128, (M + 127) / 128);
}

// ---------------- launcher ----------------
extern "C" void kernel_launch(void* const* d_in, const int* in_sizes, int n_in,
                              void* d_out, int out_size) {
    const int*   x         = (const int*)d_in[0];
    const int*   eidx      = (const int*)d_in[1];
    const int*   eattr     = (const int*)d_in[2];
    const float* edist     = (const float*)d_in[3];
    const int*   batch     = (const int*)d_in[4];
    const float* atom_emb  = (const float*)d_in[5];
    const float* att_vec   = (const float*)d_in[6];
    const float* out_lin_w = (const float*)d_in[7];
    const float* out_lin_b = (const float*)d_in[8];
    const float* g_means   = (const float*)d_in[9];
    const float* g_stds    = (const float*)d_in[10];
    const float* scale_p   = (const float*)d_in[11];
    const float* edge_emb  = (const float*)d_in[12];
    const float* mlp_w1    = (const float*)d_in[13];
    const float* mlp_b1    = (const float*)d_in[14];
    const float* mlp_w2    = (const float*)d_in[15];
    const float* mlp_b2    = (const float*)d_in[16];
    const float* bn_gamma  = (const float*)d_in[17];
    const float* bn_beta   = (const float*)d_in[18];
    const float* feat_w    = (const float*)d_in[19];
    const float* feat_b    = (const float*)d_in[20];
    const float* ol_w1     = (const float*)d_in[21];
    const float* ol_b1     = (const float*)d_in[22];
    const float* ol_w2     = (const float*)d_in[23];
    const float* ol_b2     = (const float*)d_in[24];

    const int* src = eidx;
    const int* dst = eidx + Ee;

    float *h, *agg, *mid, *hin, *stats, *gsum, *gcnt, *hg, *t1;
    int*   cnt;
    {
        void* p;
        cudaGetSymbolAddress(&p, g_h);     h     = (float*)p;
        cudaGetSymbolAddress(&p, g_agg);   agg   = (float*)p;
        cudaGetSymbolAddress(&p, g_mid);   mid   = (float*)p;
        cudaGetSymbolAddress(&p, g_hin);   hin   = (float*)p;
        cudaGetSymbolAddress(&p, g_cnt);   cnt   = (int*)p;
        cudaGetSymbolAddress(&p, g_stats); stats = (float*)p;
        cudaGetSymbolAddress(&p, g_gsum);  gsum  = (float*)p;
        cudaGetSymbolAddress(&p, g_gcnt);  gcnt  = (float*)p;
        cudaGetSymbolAddress(&p, g_hg);    hg    = (float*)p;
        cudaGetSymbolAddress(&p, g_t1);    t1    = (float*)p;
    }

    float* out_hfeat = (float*)d_out;             // [Gg, FT]
    float* out_head  = out_hfeat + Gg * FT;       // [Gg, FT2]

    const int T = 256;
    const int ND  = Nn * Dd;
    const int ED  = Ee * Dd;

    // ---- init ----
    k_zero_i<<<(Nn + T - 1) / T, T>>>(cnt, Nn);
    k_zero_f<<<(ND + T - 1) / T, T>>>(hin, ND);

    // ---- degree + gaussian basis ----
    k_count<<<(Ee + T - 1) / T, T>>>(dst);
    k_gauss<<<(ED + T - 1) / T, T>>>(edist, dst, g_means, g_stds);
    k_scale<<<(ND + T - 1) / T, T>>>(scale_p);

    // ---- attention fuse + h0 GEMM ----
    k_attn<<<(Nn * 32 + T - 1) / T, T>>>(x, atom_emb, att_vec);
    sgemm<false, true><<<gemm_grid(Nn, Dd), 256>>>(agg, out_lin_w, out_lin_b, hin, h, Nn, Dd, Dd);

    // ---- message-passing layers ----
    for (int l = 0; l < LL; l++) {
        const float* ee = edge_emb + l * 3 * 5 * Dd;
        k_agginit<<<(ND + T - 1) / T, T>>>(ee);
        k_scatter<<<(ED + T - 1) / T, T>>>(src, dst, eattr, ee);
        sgemm<true, false><<<gemm_grid(Nn, D2), 256>>>(agg, mlp_w1 + l * Dd * D2,
                                                       mlp_b1 + l * D2, nullptr, mid, Nn, Dd, D2);
        sgemm<false, false><<<gemm_grid(Nn, Dd), 256>>>(mid, mlp_w2 + l * D2 * Dd,
                                                        mlp_b2 + l * Dd, nullptr, h, Nn, D2, Dd);
        k_zero_f<<<(2 * Dd + T - 1) / T, T>>>(stats, 2 * Dd);
        k_bnstats<<<1184, T>>>();
        k_bnapply<<<(ND + T - 1) / T, T>>>(bn_gamma + l * Dd, bn_beta + l * Dd, (l < LL - 1) ? 1 : 0);
    }

    // ---- pooling ----
    k_zero_f<<<(Gg * Dd + T - 1) / T, T>>>(gsum, Gg * Dd);
    k_zero_f<<<(Gg + T - 1) / T, T>>>(gcnt, Gg);
    k_pool<<<(ND + T - 1) / T, T>>>(batch);
    k_poolcnt<<<(Nn + T - 1) / T, T>>>(batch);
    k_pooldiv<<<(Gg * Dd + T - 1) / T, T>>>();

    // ---- heads ----
    sgemm<false, false><<<gemm_grid(Gg, FT), 256>>>(hg, feat_w, feat_b, nullptr, out_hfeat, Gg, Dd, FT);
    sgemm<true, false><<<gemm_grid(Gg, FT), 256>>>(out_hfeat, ol_w1, ol_b1, nullptr, t1, Gg, FT, FT);
    sgemm<false, false><<<gemm_grid(Gg, FT2), 256>>>(t1, ol_w2, ol_b2, nullptr, out_head, Gg, FT, FT2);
}